// round 13
// baseline (speedup 1.0000x reference)
#include <cuda_runtime.h>
#include <cuda_bf16.h>
#include <math.h>
#include <cstdint>

#define BB   4
#define TT   4096
#define DD   1024
#define HH   16
#define NKV  32

// ---- device scratch (uint32 = bf16x2 words) ----
__device__ uint32_t g_xh [16384 * 512];
__device__ uint32_t g_xl [16384 * 512];
__device__ uint32_t g_wh [4][1024 * 512];
__device__ uint32_t g_wl [4][1024 * 512];
__device__ uint32_t g_Qh [64 * 4096 * 32];  // (b,h,t,d/2) bf16 hi
__device__ uint32_t g_Ql [64 * 4096 * 32];
__device__ uint32_t g_Kh [64 * 4096 * 32];
__device__ uint32_t g_Kl [64 * 4096 * 32];
__device__ uint32_t g_Vh [64 * 64 * 2048];  // (b,h,d,t/2) bf16 hi
__device__ uint32_t g_Vl [64 * 64 * 2048];  // (b,h,d,t/2) bf16 lo
__device__ uint32_t g_Oh [4 * 4096 * 512];  // (b,t,D/2) bf16 hi
__device__ uint32_t g_Ol [4 * 4096 * 512];

// ===========================================================================
// helpers
// ===========================================================================
__device__ __forceinline__ uint32_t smem_u32(const void* p) {
    uint32_t a;
    asm("{ .reg .u64 t; cvta.to.shared.u64 t, %1; cvt.u32.u64 %0, t; }"
        : "=r"(a) : "l"(p));
    return a;
}
__device__ __forceinline__ void cp16(uint32_t dst, const void* src) {
    asm volatile("cp.async.cg.shared.global [%0], [%1], 16;" :: "r"(dst), "l"(src));
}
#define CP_COMMIT() asm volatile("cp.async.commit_group;" ::: "memory")
#define CP_WAIT0()  asm volatile("cp.async.wait_group 0;" ::: "memory")
#define CP_WAIT1()  asm volatile("cp.async.wait_group 1;" ::: "memory")

__device__ __forceinline__ void mma16816(float4& d,
    uint32_t a0, uint32_t a1, uint32_t a2, uint32_t a3,
    uint32_t b0, uint32_t b1)
{
    asm volatile(
        "mma.sync.aligned.m16n8k16.row.col.f32.bf16.bf16.f32 "
        "{%0,%1,%2,%3}, {%4,%5,%6,%7}, {%8,%9}, {%0,%1,%2,%3};"
        : "+f"(d.x), "+f"(d.y), "+f"(d.z), "+f"(d.w)
        : "r"(a0), "r"(a1), "r"(a2), "r"(a3), "r"(b0), "r"(b1));
}
__device__ __forceinline__ uint32_t pack_hi(float a, float b) {
    __nv_bfloat162 t = __floats2bfloat162_rn(a, b);
    return *(uint32_t*)&t;
}
__device__ __forceinline__ uint32_t pack_lo(float a, float b, uint32_t hi) {
    __nv_bfloat162 h = *(__nv_bfloat162*)&hi;
    __nv_bfloat162 t = __floats2bfloat162_rn(a - __bfloat162float(h.x),
                                             b - __bfloat162float(h.y));
    return *(uint32_t*)&t;
}

// ===========================================================================
// fp32 -> bf16 hi/lo split (once per tensor)
// ===========================================================================
__global__ void cvt_hl(const float4* __restrict__ src, uint2* __restrict__ h,
                       uint2* __restrict__ l, int n4)
{
    int i = blockIdx.x * 256 + threadIdx.x;
    if (i >= n4) return;
    float4 v = src[i];
    uint32_t h0 = pack_hi(v.x, v.y), h1 = pack_hi(v.z, v.w);
    h[i] = make_uint2(h0, h1);
    l[i] = make_uint2(pack_lo(v.x, v.y, h0), pack_lo(v.z, v.w, h1));
}

// ===========================================================================
// bf16 hi/lo GEMM v2: tile 64(M) x 128(N), 256 thr (8 warps as 2x4,
// warp-tile 32x32), acc = 32 regs/thread -> ~90 live regs under the 128 cap
// leaving prefetch headroom. 3-stage cp.async pipeline (wait_group 1).
// mode 0: f32 (B,T,D)    mode 1: bf16 h/l head-split (b,h,t,d)
// mode 2: bf16 h/l head-split transposed (b,h,d,t)
// ===========================================================================
#define GSTR 20
#define GA_H 0
#define GA_L 1280
#define GW_H 2560
#define GW_L 5120
#define GBUF 7680
#define EP_STR 129
#define GEMM_SMEM_B (3 * GBUF * 4)   // 92160

__global__ __launch_bounds__(256, 2)
void gemm_bf16(const uint32_t* __restrict__ Ah, const uint32_t* __restrict__ Al,
               const uint32_t* __restrict__ Wh, const uint32_t* __restrict__ Wl,
               const float* __restrict__ bias,
               float* __restrict__ C0, uint32_t* __restrict__ Ch,
               uint32_t* __restrict__ Cl, int mode)
{
    extern __shared__ uint32_t sw[];
    const uint32_t sbase = smem_u32(sw);
    const int tid = threadIdx.x, lane = tid & 31, wid = tid >> 5;
    const int wm = wid >> 2, wn = wid & 3;            // 2 x 4 warp grid
    const int n0 = blockIdx.x * 128, m0 = blockIdx.y * 64;
    const int r0 = lane >> 2, c2l = lane & 3;

    auto fill = [&](int kc) {
        int buf = kc % 3;
        int kt = kc * 32;
#pragma unroll
        for (int it = 0; it < 6; it++) {
            int e = tid + it * 256;                    // 0..1535
            if (it < 2) {                              // A hi/lo: 512 chunks
                int arr = e >> 8;
                int c = e & 255, row = c >> 2, cw = (c & 3) * 4;
                const uint32_t* g = arr ? Al : Ah;
                uint32_t dw = (uint32_t)(buf * GBUF + arr * 1280 + row * GSTR + cw);
                cp16(sbase + dw * 4, g + (size_t)(m0 + row) * 512 + (kt >> 1) + cw);
            } else {                                   // W hi/lo: 1024 chunks
                int e2 = e - 512;
                int arr = e2 >> 9;
                int c = e2 & 511, row = c >> 2, cw = (c & 3) * 4;
                const uint32_t* g = arr ? Wl : Wh;
                uint32_t dw = (uint32_t)(buf * GBUF + GW_H + arr * 2560 + row * GSTR + cw);
                cp16(sbase + dw * 4, g + (size_t)(n0 + row) * 512 + (kt >> 1) + cw);
            }
        }
    };

    float4 acc[2][4];
#pragma unroll
    for (int mt = 0; mt < 2; mt++)
#pragma unroll
        for (int nt = 0; nt < 4; nt++) acc[mt][nt] = make_float4(0.f, 0.f, 0.f, 0.f);

    fill(0); CP_COMMIT();
    fill(1); CP_COMMIT();

    for (int kc = 0; kc < 32; kc++) {
        CP_WAIT1();
        __syncthreads();
        if (kc + 2 < 32) fill(kc + 2);
        CP_COMMIT();
        const uint32_t* sb = sw + (kc % 3) * GBUF;

#pragma unroll
        for (int ks = 0; ks < 2; ks++) {
            uint32_t AH[2][4], AL[2][4];
#pragma unroll
            for (int mt = 0; mt < 2; mt++) {
                int aw = (wm * 32 + mt * 16 + r0) * GSTR + c2l + ks * 8;
                AH[mt][0] = sb[GA_H + aw];
                AH[mt][1] = sb[GA_H + aw + 8 * GSTR];
                AH[mt][2] = sb[GA_H + aw + 4];
                AH[mt][3] = sb[GA_H + aw + 8 * GSTR + 4];
                AL[mt][0] = sb[GA_L + aw];
                AL[mt][1] = sb[GA_L + aw + 8 * GSTR];
                AL[mt][2] = sb[GA_L + aw + 4];
                AL[mt][3] = sb[GA_L + aw + 8 * GSTR + 4];
            }
#pragma unroll
            for (int nt = 0; nt < 4; nt++) {
                int bw = (wn * 32 + nt * 8 + r0) * GSTR + c2l + ks * 8;
                uint32_t bh0 = sb[GW_H + bw], bh1 = sb[GW_H + bw + 4];
                uint32_t bl0 = sb[GW_L + bw], bl1 = sb[GW_L + bw + 4];
#pragma unroll
                for (int mt = 0; mt < 2; mt++) {
                    mma16816(acc[mt][nt], AH[mt][0], AH[mt][1], AH[mt][2], AH[mt][3], bh0, bh1);
                    mma16816(acc[mt][nt], AL[mt][0], AL[mt][1], AL[mt][2], AL[mt][3], bh0, bh1);
                    mma16816(acc[mt][nt], AH[mt][0], AH[mt][1], AH[mt][2], AH[mt][3], bl0, bl1);
                }
            }
        }
        __syncthreads();
    }

    // ---- epilogues ----
    if (mode == 0) {
#pragma unroll
        for (int mt = 0; mt < 2; mt++) {
            int rowa = wm * 32 + mt * 16 + r0;
#pragma unroll
            for (int nt = 0; nt < 4; nt++) {
                int col = wn * 32 + nt * 8 + c2l * 2;
                float b0 = bias[n0 + col], b1 = bias[n0 + col + 1];
                *(float2*)&C0[(size_t)(m0 + rowa) * 1024 + n0 + col] =
                    make_float2(acc[mt][nt].x + b0, acc[mt][nt].y + b1);
                *(float2*)&C0[(size_t)(m0 + rowa + 8) * 1024 + n0 + col] =
                    make_float2(acc[mt][nt].z + b0, acc[mt][nt].w + b1);
            }
        }
    } else if (mode == 1) {
#pragma unroll
        for (int mt = 0; mt < 2; mt++) {
            int rowa = wm * 32 + mt * 16 + r0;
            int ma = m0 + rowa;
            int ba = ma >> 12, ta = ma & 4095;
#pragma unroll
            for (int nt = 0; nt < 4; nt++) {
                int col = n0 + wn * 32 + nt * 8 + c2l * 2;
                int hh = col >> 6, dcol = col & 63;
                float b0 = bias[col], b1 = bias[col + 1];
                float v0x = acc[mt][nt].x + b0, v0y = acc[mt][nt].y + b1;
                float v1x = acc[mt][nt].z + b0, v1y = acc[mt][nt].w + b1;
                size_t w0 = ((size_t)(ba * 16 + hh) * 4096 + ta) * 32 + (dcol >> 1);
                uint32_t hw = pack_hi(v0x, v0y);
                Ch[w0] = hw;  Cl[w0] = pack_lo(v0x, v0y, hw);
                hw = pack_hi(v1x, v1y);
                Ch[w0 + 8 * 32] = hw;  Cl[w0 + 8 * 32] = pack_lo(v1x, v1y, hw);
            }
        }
    } else {
        // V: transpose 64x128 tile through smem -> (b,h,d,t) bf16 hi/lo
        __syncthreads();
        float* sf = (float*)sw;
#pragma unroll
        for (int mt = 0; mt < 2; mt++) {
            int rowa = wm * 32 + mt * 16 + r0;
#pragma unroll
            for (int nt = 0; nt < 4; nt++) {
                int col = wn * 32 + nt * 8 + c2l * 2;
                float b0 = bias[n0 + col], b1 = bias[n0 + col + 1];
                sf[rowa * EP_STR + col]           = acc[mt][nt].x + b0;
                sf[rowa * EP_STR + col + 1]       = acc[mt][nt].y + b1;
                sf[(rowa + 8) * EP_STR + col]     = acc[mt][nt].z + b0;
                sf[(rowa + 8) * EP_STR + col + 1] = acc[mt][nt].w + b1;
            }
        }
        __syncthreads();
        const int ba = m0 >> 12, t0 = m0 & 4095;
#pragma unroll
        for (int it = 0; it < 8; it++) {
            int e = tid + it * 256;                    // 0..2047
            int col = e >> 4, r4 = e & 15;             // 128 cols x 16 row-quads
            float o0 = sf[(r4 * 4 + 0) * EP_STR + col];
            float o1 = sf[(r4 * 4 + 1) * EP_STR + col];
            float o2 = sf[(r4 * 4 + 2) * EP_STR + col];
            float o3 = sf[(r4 * 4 + 3) * EP_STR + col];
            int n = n0 + col, hh = n >> 6, dcol = n & 63;
            size_t w = ((size_t)((ba * 16 + hh) * 64 + dcol)) * 2048 + (t0 >> 1) + r4 * 2;
            uint32_t h0 = pack_hi(o0, o1), h1 = pack_hi(o2, o3);
            *(uint2*)&Ch[w] = make_uint2(h0, h1);
            *(uint2*)&Cl[w] = make_uint2(pack_lo(o0, o1, h0), pack_lo(o2, o3, h1));
        }
    }
}

// ===========================================================================
// attention: unchanged R10 champion.
// ===========================================================================
#define KHI_W 0
#define KLO_W 4608          // 128*36
#define VHI_W 9216
#define VLO_W 13568         // + 64*68
#define ABUF  17920
#define SMEM_ATTN_B (2 * ABUF * 4)   // 143360

__global__ __launch_bounds__(256, 1)
void attn_mma(const uint32_t* __restrict__ Qh, const uint32_t* __restrict__ Ql,
              const uint32_t* __restrict__ Kh, const uint32_t* __restrict__ Kl,
              const uint32_t* __restrict__ Vh, const uint32_t* __restrict__ Vl,
              uint32_t* __restrict__ Oh, uint32_t* __restrict__ Ol)
{
    extern __shared__ uint32_t sm[];
    const uint32_t sbase = smem_u32(sm);
    const int tid  = threadIdx.x;
    const int lane = tid & 31, wid = tid >> 5;
    const int bh = blockIdx.y, q0 = blockIdx.x * 128;
    const int b = bh >> 4, h = bh & 15;
    const int r0 = lane >> 2;

    auto fill = [&](int buf, int j) {
#pragma unroll
        for (int it = 0; it < 16; it++) {
            int e = tid + it * 256;
            if (it < 8) {
                int arr = e >> 10;
                int c = e & 1023, row = c >> 3, cw = (c & 7) * 4;
                const uint32_t* g = arr ? Kl : Kh;
                uint32_t dw = (uint32_t)(buf * ABUF + arr * 4608 + row * 36 + cw);
                cp16(sbase + dw * 4,
                     g + ((size_t)bh * 4096 + j * 128 + row) * 32 + cw);
            } else {
                int e2 = e - 2048;
                int arr = e2 >> 10;
                int c = e2 & 1023, row = c >> 4, cw = (c & 15) * 4;
                const uint32_t* g = arr ? Vl : Vh;
                uint32_t dw = (uint32_t)(buf * ABUF + VHI_W + arr * 4352 + row * 68 + cw);
                cp16(sbase + dw * 4,
                     g + ((size_t)bh * 64 + row) * 2048 + j * 64 + cw);
            }
        }
    };

    uint32_t QH[16], QL[16];
    {
        const uint32_t* gqh = Qh + ((size_t)bh * 4096 + q0 + wid * 16) * 32;
        const uint32_t* gql = Ql + ((size_t)bh * 4096 + q0 + wid * 16) * 32;
#pragma unroll
        for (int ks = 0; ks < 4; ks++)
#pragma unroll
            for (int ko = 0; ko < 2; ko++)
#pragma unroll
                for (int ro = 0; ro < 2; ro++) {
                    int off = (r0 + 8 * ro) * 32 + ks * 8 + ko * 4 + (lane & 3);
                    int idx = ks * 4 + ko * 2 + ro;
                    QH[idx] = gqh[off];
                    QL[idx] = gql[off];
                }
    }

    float4 Oacc[8];
#pragma unroll
    for (int i = 0; i < 8; i++) Oacc[i] = make_float4(0.f, 0.f, 0.f, 0.f);
    float m0 = -INFINITY, m1 = -INFINITY, l0 = 0.f, l1 = 0.f;

    const int kbase = (lane >> 2) * 36 + (lane & 3);
    const int vbase = (lane >> 2) * 68 + (lane & 3);

    fill(0, 0); CP_COMMIT();

    for (int j = 0; j < NKV; j++) {
        CP_WAIT0();
        __syncthreads();
        if (j + 1 < NKV) fill((j + 1) & 1, j + 1);
        CP_COMMIT();
        const uint32_t* sb = sm + (j & 1) * ABUF;

        float4 Sacc[16];
#pragma unroll
        for (int nt = 0; nt < 16; nt++) {
            float4 acc = make_float4(0.f, 0.f, 0.f, 0.f);
            int nb = nt * (8 * 36);
#pragma unroll
            for (int ks = 0; ks < 4; ks++) {
                int wA = kbase + nb + ks * 8;
                uint32_t bh0 = sb[KHI_W + wA], bh1 = sb[KHI_W + wA + 4];
                uint32_t bl0 = sb[KLO_W + wA], bl1 = sb[KLO_W + wA + 4];
                int q = ks * 4;
                mma16816(acc, QH[q], QH[q+1], QH[q+2], QH[q+3], bh0, bh1);
                mma16816(acc, QH[q], QH[q+1], QH[q+2], QH[q+3], bl0, bl1);
                mma16816(acc, QL[q], QL[q+1], QL[q+2], QL[q+3], bh0, bh1);
            }
            Sacc[nt] = acc;
        }

        float mx0 = -INFINITY, mx1 = -INFINITY;
#pragma unroll
        for (int nt = 0; nt < 16; nt++) {
            mx0 = fmaxf(mx0, fmaxf(Sacc[nt].x, Sacc[nt].y));
            mx1 = fmaxf(mx1, fmaxf(Sacc[nt].z, Sacc[nt].w));
        }
        mx0 = fmaxf(mx0, __shfl_xor_sync(0xffffffffu, mx0, 1));
        mx0 = fmaxf(mx0, __shfl_xor_sync(0xffffffffu, mx0, 2));
        mx1 = fmaxf(mx1, __shfl_xor_sync(0xffffffffu, mx1, 1));
        mx1 = fmaxf(mx1, __shfl_xor_sync(0xffffffffu, mx1, 2));
        float mn0 = fmaxf(m0, mx0), mn1 = fmaxf(m1, mx1);

        float s0 = 0.f, s1 = 0.f;
#pragma unroll
        for (int s = 0; s < 8; s++) {
            float4 Sa = Sacc[2 * s], Sb = Sacc[2 * s + 1];
            float pa0 = __expf(Sa.x - mn0), pa1 = __expf(Sa.y - mn0);
            float pa2 = __expf(Sa.z - mn1), pa3 = __expf(Sa.w - mn1);
            float pb0 = __expf(Sb.x - mn0), pb1 = __expf(Sb.y - mn0);
            float pb2 = __expf(Sb.z - mn1), pb3 = __expf(Sb.w - mn1);
            s0 += pa0 + pa1 + pb0 + pb1;
            s1 += pa2 + pa3 + pb2 + pb3;
            uint32_t ah0 = pack_hi(pa0, pa1), al0 = pack_lo(pa0, pa1, ah0);
            uint32_t ah1 = pack_hi(pa2, pa3), al1 = pack_lo(pa2, pa3, ah1);
            uint32_t ah2 = pack_hi(pb0, pb1), al2 = pack_lo(pb0, pb1, ah2);
            uint32_t ah3 = pack_hi(pb2, pb3), al3 = pack_lo(pb2, pb3, ah3);
#pragma unroll
            for (int nt = 0; nt < 8; nt++) {
                int wB = vbase + nt * (8 * 68) + s * 8;
                uint32_t vh0 = sb[VHI_W + wB], vh1 = sb[VHI_W + wB + 4];
                uint32_t vl0 = sb[VLO_W + wB], vl1 = sb[VLO_W + wB + 4];
                mma16816(Oacc[nt], ah0, ah1, ah2, ah3, vh0, vh1);
                mma16816(Oacc[nt], al0, al1, al2, al3, vh0, vh1);
                mma16816(Oacc[nt], ah0, ah1, ah2, ah3, vl0, vl1);
            }
        }

        s0 += __shfl_xor_sync(0xffffffffu, s0, 1);
        s0 += __shfl_xor_sync(0xffffffffu, s0, 2);
        s1 += __shfl_xor_sync(0xffffffffu, s1, 1);
        s1 += __shfl_xor_sync(0xffffffffu, s1, 2);
        l0 = __expf(m0 - mn0) * l0 + s0;   m0 = mn0;
        l1 = __expf(m1 - mn1) * l1 + s1;   m1 = mn1;
    }

    const float inv0 = 1.f / l0, inv1 = 1.f / l1;
    const int rowg = q0 + wid * 16 + r0;
    uint32_t* oh = Oh + ((size_t)b * 4096 + rowg) * 512 + h * 32 + (lane & 3);
    uint32_t* ol = Ol + ((size_t)b * 4096 + rowg) * 512 + h * 32 + (lane & 3);
#pragma unroll
    for (int nt = 0; nt < 8; nt++) {
        float ax = Oacc[nt].x * inv0, ay = Oacc[nt].y * inv0;
        uint32_t hw = pack_hi(ax, ay);
        oh[nt * 4] = hw;  ol[nt * 4] = pack_lo(ax, ay, hw);
        float az = Oacc[nt].z * inv1, aw = Oacc[nt].w * inv1;
        hw = pack_hi(az, aw);
        oh[nt * 4 + 8 * 512] = hw;  ol[nt * 4 + 8 * 512] = pack_lo(az, aw, hw);
    }
}

// ===========================================================================
extern "C" void kernel_launch(void* const* d_in, const int* in_sizes, int n_in,
                              void* d_out, int out_size)
{
    const float* x  = (const float*)d_in[0];
    const float* wq = (const float*)d_in[1];
    const float* bq = (const float*)d_in[2];
    const float* wk = (const float*)d_in[3];
    const float* bk = (const float*)d_in[4];
    const float* wv = (const float*)d_in[5];
    const float* bv = (const float*)d_in[6];
    const float* wo = (const float*)d_in[7];
    const float* bo = (const float*)d_in[8];
    float* out = (float*)d_out;

    uint32_t *xh, *xl, *wh, *wl, *Qh, *Ql, *Kh, *Kl, *Vh, *Vl, *Ohp, *Olp;
    cudaGetSymbolAddress((void**)&xh, g_xh);
    cudaGetSymbolAddress((void**)&xl, g_xl);
    cudaGetSymbolAddress((void**)&wh, g_wh);
    cudaGetSymbolAddress((void**)&wl, g_wl);
    cudaGetSymbolAddress((void**)&Qh, g_Qh);
    cudaGetSymbolAddress((void**)&Ql, g_Ql);
    cudaGetSymbolAddress((void**)&Kh, g_Kh);
    cudaGetSymbolAddress((void**)&Kl, g_Kl);
    cudaGetSymbolAddress((void**)&Vh, g_Vh);
    cudaGetSymbolAddress((void**)&Vl, g_Vl);
    cudaGetSymbolAddress((void**)&Ohp, g_Oh);
    cudaGetSymbolAddress((void**)&Olp, g_Ol);

    cudaFuncSetAttribute(attn_mma,
                         cudaFuncAttributeMaxDynamicSharedMemorySize, SMEM_ATTN_B);
    cudaFuncSetAttribute(gemm_bf16,
                         cudaFuncAttributeMaxDynamicSharedMemorySize, GEMM_SMEM_B);

    const int WW = 1024 * 512;

    cvt_hl<<<16384, 256>>>((const float4*)x,  (uint2*)xh, (uint2*)xl, 4194304);
    cvt_hl<<<1024, 256>>>((const float4*)wq, (uint2*)(wh + 0*WW), (uint2*)(wl + 0*WW), 262144);
    cvt_hl<<<1024, 256>>>((const float4*)wk, (uint2*)(wh + 1*WW), (uint2*)(wl + 1*WW), 262144);
    cvt_hl<<<1024, 256>>>((const float4*)wv, (uint2*)(wh + 2*WW), (uint2*)(wl + 2*WW), 262144);
    cvt_hl<<<1024, 256>>>((const float4*)wo, (uint2*)(wh + 3*WW), (uint2*)(wl + 3*WW), 262144);

    dim3 gg(8, 256);   // N/128 x M/64
    gemm_bf16<<<gg, 256, GEMM_SMEM_B>>>(xh, xl, wh + 0*WW, wl + 0*WW, bq,
                                        nullptr, Qh, Ql, 1);
    gemm_bf16<<<gg, 256, GEMM_SMEM_B>>>(xh, xl, wh + 1*WW, wl + 1*WW, bk,
                                        nullptr, Kh, Kl, 1);
    gemm_bf16<<<gg, 256, GEMM_SMEM_B>>>(xh, xl, wh + 2*WW, wl + 2*WW, bv,
                                        nullptr, Vh, Vl, 2);

    attn_mma<<<dim3(32, 64), 256, SMEM_ATTN_B>>>(Qh, Ql, Kh, Kl, Vh, Vl, Ohp, Olp);

    gemm_bf16<<<gg, 256, GEMM_SMEM_B>>>(Ohp, Olp, wh + 3*WW, wl + 3*WW, bo,
                                        out, nullptr, nullptr, 0);
}

// round 14
// speedup vs baseline: 1.0764x; 1.0764x over previous
#include <cuda_runtime.h>
#include <cuda_bf16.h>
#include <math.h>
#include <cstdint>

#define BB   4
#define TT   4096
#define DD   1024
#define HH   16
#define NKV  32
#define LOG2E 1.4426950408889634f

// ---- device scratch (uint32 = bf16x2 words) ----
__device__ uint32_t g_xh [16384 * 512];
__device__ uint32_t g_xl [16384 * 512];
__device__ uint32_t g_wh [4][1024 * 512];
__device__ uint32_t g_wl [4][1024 * 512];
__device__ uint32_t g_Qh [64 * 4096 * 32];  // (b,h,t,d/2) bf16 hi (pre-scaled by log2e)
__device__ uint32_t g_Ql [64 * 4096 * 32];
__device__ uint32_t g_Kh [64 * 4096 * 32];
__device__ uint32_t g_Kl [64 * 4096 * 32];
__device__ uint32_t g_Vh [64 * 64 * 2048];  // (b,h,d,t/2) bf16 hi
__device__ uint32_t g_Vl [64 * 64 * 2048];  // (b,h,d,t/2) bf16 lo
__device__ uint32_t g_Oh [4 * 4096 * 512];  // (b,t,D/2) bf16 hi
__device__ uint32_t g_Ol [4 * 4096 * 512];

// ===========================================================================
// helpers
// ===========================================================================
__device__ __forceinline__ uint32_t smem_u32(const void* p) {
    uint32_t a;
    asm("{ .reg .u64 t; cvta.to.shared.u64 t, %1; cvt.u32.u64 %0, t; }"
        : "=r"(a) : "l"(p));
    return a;
}
__device__ __forceinline__ void cp16(uint32_t dst, const void* src) {
    asm volatile("cp.async.cg.shared.global [%0], [%1], 16;" :: "r"(dst), "l"(src));
}
#define CP_COMMIT() asm volatile("cp.async.commit_group;" ::: "memory")
#define CP_WAIT0()  asm volatile("cp.async.wait_group 0;" ::: "memory")

__device__ __forceinline__ void mma16816(float4& d,
    uint32_t a0, uint32_t a1, uint32_t a2, uint32_t a3,
    uint32_t b0, uint32_t b1)
{
    asm volatile(
        "mma.sync.aligned.m16n8k16.row.col.f32.bf16.bf16.f32 "
        "{%0,%1,%2,%3}, {%4,%5,%6,%7}, {%8,%9}, {%0,%1,%2,%3};"
        : "+f"(d.x), "+f"(d.y), "+f"(d.z), "+f"(d.w)
        : "r"(a0), "r"(a1), "r"(a2), "r"(a3), "r"(b0), "r"(b1));
}
__device__ __forceinline__ uint32_t pack_hi(float a, float b) {
    __nv_bfloat162 t = __floats2bfloat162_rn(a, b);
    return *(uint32_t*)&t;
}
__device__ __forceinline__ uint32_t pack_lo(float a, float b, uint32_t hi) {
    __nv_bfloat162 h = *(__nv_bfloat162*)&hi;
    __nv_bfloat162 t = __floats2bfloat162_rn(a - __bfloat162float(h.x),
                                             b - __bfloat162float(h.y));
    return *(uint32_t*)&t;
}
__device__ __forceinline__ float ex2(float x) {
    float r;
    asm("ex2.approx.f32 %0, %1;" : "=f"(r) : "f"(x));
    return r;
}

// ===========================================================================
// fp32 -> bf16 hi/lo split: x (single) and all-4-weights (merged) variants
// ===========================================================================
__global__ void cvt_hl(const float4* __restrict__ src, uint2* __restrict__ h,
                       uint2* __restrict__ l, int n4)
{
    int i = blockIdx.x * 256 + threadIdx.x;
    if (i >= n4) return;
    float4 v = src[i];
    uint32_t h0 = pack_hi(v.x, v.y), h1 = pack_hi(v.z, v.w);
    h[i] = make_uint2(h0, h1);
    l[i] = make_uint2(pack_lo(v.x, v.y, h0), pack_lo(v.z, v.w, h1));
}
__global__ void cvt_w4(const float4* __restrict__ w0, const float4* __restrict__ w1,
                       const float4* __restrict__ w2, const float4* __restrict__ w3,
                       uint2* __restrict__ h, uint2* __restrict__ l)
{
    int i = blockIdx.x * 256 + threadIdx.x;       // 0 .. 4*262144-1
    int m = i >> 18, o = i & 262143;
    const float4* s = (m == 0) ? w0 : (m == 1) ? w1 : (m == 2) ? w2 : w3;
    float4 v = s[o];
    uint32_t h0 = pack_hi(v.x, v.y), h1 = pack_hi(v.z, v.w);
    h[i] = make_uint2(h0, h1);
    l[i] = make_uint2(pack_lo(v.x, v.y, h0), pack_lo(v.z, v.w, h1));
}

// ===========================================================================
// bf16 hi/lo GEMM, 128x128, 2 CTA/SM, cp.async dbl buffer (R10 proven).
// mode 0: f32 (B,T,D)  mode 1: bf16 h/l head-split (b,h,t,d), scaled by oscale
// mode 2: bf16 h/l head-split transposed (b,h,d,t)
// ===========================================================================
#define GSTR 20
#define GA_H 0
#define GA_L 2560
#define GW_H 5120
#define GW_L 7680
#define GBUF 10240
#define EP_STR 129
#define GEMM_SMEM_B (2 * GBUF * 4)

__global__ __launch_bounds__(256, 2)
void gemm_bf16(const uint32_t* __restrict__ Ah, const uint32_t* __restrict__ Al,
               const uint32_t* __restrict__ Wh, const uint32_t* __restrict__ Wl,
               const float* __restrict__ bias,
               float* __restrict__ C0, uint32_t* __restrict__ Ch,
               uint32_t* __restrict__ Cl, int mode, float oscale)
{
    extern __shared__ uint32_t sw[];
    const uint32_t sbase = smem_u32(sw);
    const int tid = threadIdx.x, lane = tid & 31, wid = tid >> 5;
    const int wm = wid >> 1, wn = wid & 1;
    const int n0 = blockIdx.x * 128, m0 = blockIdx.y * 128;
    const int r0 = lane >> 2, c2l = lane & 3;

    auto fill = [&](int buf, int kt) {
#pragma unroll
        for (int it = 0; it < 8; it++) {
            int e = tid + it * 256;
            int arr = e >> 9;
            int c = e & 511, row = c >> 2, cw = (c & 3) * 4;
            const uint32_t* g = (arr == 0) ? Ah : (arr == 1) ? Al
                              : (arr == 2) ? Wh : Wl;
            int rbase = (arr < 2) ? m0 : n0;
            uint32_t dw = (uint32_t)(buf * GBUF + arr * 2560 + row * GSTR + cw);
            cp16(sbase + dw * 4, g + (size_t)(rbase + row) * 512 + (kt >> 1) + cw);
        }
    };

    float4 acc[2][8];
#pragma unroll
    for (int mt = 0; mt < 2; mt++)
#pragma unroll
        for (int nt = 0; nt < 8; nt++) acc[mt][nt] = make_float4(0.f, 0.f, 0.f, 0.f);

    fill(0, 0); CP_COMMIT();

    for (int kc = 0; kc < 32; kc++) {
        CP_WAIT0();
        __syncthreads();
        if (kc + 1 < 32) fill((kc + 1) & 1, (kc + 1) * 32);
        CP_COMMIT();
        const uint32_t* sb = sw + (kc & 1) * GBUF;

#pragma unroll
        for (int ks = 0; ks < 2; ks++) {
            uint32_t AH[2][4], AL[2][4];
#pragma unroll
            for (int mt = 0; mt < 2; mt++) {
                int aw = (wm * 32 + mt * 16 + r0) * GSTR + c2l + ks * 8;
                AH[mt][0] = sb[GA_H + aw];
                AH[mt][1] = sb[GA_H + aw + 8 * GSTR];
                AH[mt][2] = sb[GA_H + aw + 4];
                AH[mt][3] = sb[GA_H + aw + 8 * GSTR + 4];
                AL[mt][0] = sb[GA_L + aw];
                AL[mt][1] = sb[GA_L + aw + 8 * GSTR];
                AL[mt][2] = sb[GA_L + aw + 4];
                AL[mt][3] = sb[GA_L + aw + 8 * GSTR + 4];
            }
#pragma unroll
            for (int nt = 0; nt < 8; nt++) {
                int bw = (wn * 64 + nt * 8 + r0) * GSTR + c2l + ks * 8;
                uint32_t bh0 = sb[GW_H + bw], bh1 = sb[GW_H + bw + 4];
                uint32_t bl0 = sb[GW_L + bw], bl1 = sb[GW_L + bw + 4];
#pragma unroll
                for (int mt = 0; mt < 2; mt++) {
                    mma16816(acc[mt][nt], AH[mt][0], AH[mt][1], AH[mt][2], AH[mt][3], bh0, bh1);
                    mma16816(acc[mt][nt], AL[mt][0], AL[mt][1], AL[mt][2], AL[mt][3], bh0, bh1);
                    mma16816(acc[mt][nt], AH[mt][0], AH[mt][1], AH[mt][2], AH[mt][3], bl0, bl1);
                }
            }
        }
        __syncthreads();
    }

    // ---- epilogues ----
    if (mode == 0) {
#pragma unroll
        for (int mt = 0; mt < 2; mt++) {
            int rowa = wm * 32 + mt * 16 + r0;
#pragma unroll
            for (int nt = 0; nt < 8; nt++) {
                int col = wn * 64 + nt * 8 + c2l * 2;
                float b0 = bias[n0 + col], b1 = bias[n0 + col + 1];
                *(float2*)&C0[(size_t)(m0 + rowa) * 1024 + n0 + col] =
                    make_float2(acc[mt][nt].x + b0, acc[mt][nt].y + b1);
                *(float2*)&C0[(size_t)(m0 + rowa + 8) * 1024 + n0 + col] =
                    make_float2(acc[mt][nt].z + b0, acc[mt][nt].w + b1);
            }
        }
    } else if (mode == 1) {
#pragma unroll
        for (int mt = 0; mt < 2; mt++) {
            int rowa = wm * 32 + mt * 16 + r0;
            int ma = m0 + rowa;
            int ba = ma >> 12, ta = ma & 4095;
#pragma unroll
            for (int nt = 0; nt < 8; nt++) {
                int col = wn * 64 + nt * 8 + c2l * 2;
                int n = n0 + col, hh = n >> 6, dcol = n & 63;
                float b0 = bias[n], b1 = bias[n + 1];
                float v0x = (acc[mt][nt].x + b0) * oscale;
                float v0y = (acc[mt][nt].y + b1) * oscale;
                float v1x = (acc[mt][nt].z + b0) * oscale;
                float v1y = (acc[mt][nt].w + b1) * oscale;
                size_t w0 = ((size_t)(ba * 16 + hh) * 4096 + ta) * 32 + (dcol >> 1);
                uint32_t hw = pack_hi(v0x, v0y);
                Ch[w0] = hw;  Cl[w0] = pack_lo(v0x, v0y, hw);
                hw = pack_hi(v1x, v1y);
                Ch[w0 + 8 * 32] = hw;  Cl[w0 + 8 * 32] = pack_lo(v1x, v1y, hw);
            }
        }
    } else {
        __syncthreads();
        float* sf = (float*)sw;
#pragma unroll
        for (int mt = 0; mt < 2; mt++) {
            int rowa = wm * 32 + mt * 16 + r0;
#pragma unroll
            for (int nt = 0; nt < 8; nt++) {
                int col = wn * 64 + nt * 8 + c2l * 2;
                float b0 = bias[n0 + col], b1 = bias[n0 + col + 1];
                sf[rowa * EP_STR + col]           = acc[mt][nt].x + b0;
                sf[rowa * EP_STR + col + 1]       = acc[mt][nt].y + b1;
                sf[(rowa + 8) * EP_STR + col]     = acc[mt][nt].z + b0;
                sf[(rowa + 8) * EP_STR + col + 1] = acc[mt][nt].w + b1;
            }
        }
        __syncthreads();
        const int ba = m0 >> 12, t0 = m0 & 4095;
#pragma unroll
        for (int it = 0; it < 16; it++) {
            int e = tid + it * 256;
            int col = e >> 5, r4 = e & 31;
            float o0 = sf[(r4 * 4 + 0) * EP_STR + col];
            float o1 = sf[(r4 * 4 + 1) * EP_STR + col];
            float o2 = sf[(r4 * 4 + 2) * EP_STR + col];
            float o3 = sf[(r4 * 4 + 3) * EP_STR + col];
            int n = n0 + col, hh = n >> 6, dcol = n & 63;
            size_t w = ((size_t)((ba * 16 + hh) * 64 + dcol)) * 2048 + (t0 >> 1) + r4 * 2;
            uint32_t h0 = pack_hi(o0, o1), h1 = pack_hi(o2, o3);
            *(uint2*)&Ch[w] = make_uint2(h0, h1);
            *(uint2*)&Cl[w] = make_uint2(pack_lo(o0, o1, h0), pack_lo(o2, o3, h1));
        }
    }
}

// ===========================================================================
// attention: R10 champion structure; softmax in log2 domain (Q pre-scaled by
// log2e, exp2 via bare MUFU.EX2). O never rescaled (reference bug).
// ===========================================================================
#define KHI_W 0
#define KLO_W 4608          // 128*36
#define VHI_W 9216
#define VLO_W 13568         // + 64*68
#define ABUF  17920
#define SMEM_ATTN_B (2 * ABUF * 4)   // 143360

__global__ __launch_bounds__(256, 1)
void attn_mma(const uint32_t* __restrict__ Qh, const uint32_t* __restrict__ Ql,
              const uint32_t* __restrict__ Kh, const uint32_t* __restrict__ Kl,
              const uint32_t* __restrict__ Vh, const uint32_t* __restrict__ Vl,
              uint32_t* __restrict__ Oh, uint32_t* __restrict__ Ol)
{
    extern __shared__ uint32_t sm[];
    const uint32_t sbase = smem_u32(sm);
    const int tid  = threadIdx.x;
    const int lane = tid & 31, wid = tid >> 5;
    const int bh = blockIdx.y, q0 = blockIdx.x * 128;
    const int b = bh >> 4, h = bh & 15;
    const int r0 = lane >> 2;

    auto fill = [&](int buf, int j) {
#pragma unroll
        for (int it = 0; it < 16; it++) {
            int e = tid + it * 256;
            if (it < 8) {
                int arr = e >> 10;
                int c = e & 1023, row = c >> 3, cw = (c & 7) * 4;
                const uint32_t* g = arr ? Kl : Kh;
                uint32_t dw = (uint32_t)(buf * ABUF + arr * 4608 + row * 36 + cw);
                cp16(sbase + dw * 4,
                     g + ((size_t)bh * 4096 + j * 128 + row) * 32 + cw);
            } else {
                int e2 = e - 2048;
                int arr = e2 >> 10;
                int c = e2 & 1023, row = c >> 4, cw = (c & 15) * 4;
                const uint32_t* g = arr ? Vl : Vh;
                uint32_t dw = (uint32_t)(buf * ABUF + VHI_W + arr * 4352 + row * 68 + cw);
                cp16(sbase + dw * 4,
                     g + ((size_t)bh * 64 + row) * 2048 + j * 64 + cw);
            }
        }
    };

    uint32_t QH[16], QL[16];
    {
        const uint32_t* gqh = Qh + ((size_t)bh * 4096 + q0 + wid * 16) * 32;
        const uint32_t* gql = Ql + ((size_t)bh * 4096 + q0 + wid * 16) * 32;
#pragma unroll
        for (int ks = 0; ks < 4; ks++)
#pragma unroll
            for (int ko = 0; ko < 2; ko++)
#pragma unroll
                for (int ro = 0; ro < 2; ro++) {
                    int off = (r0 + 8 * ro) * 32 + ks * 8 + ko * 4 + (lane & 3);
                    int idx = ks * 4 + ko * 2 + ro;
                    QH[idx] = gqh[off];
                    QL[idx] = gql[off];
                }
    }

    float4 Oacc[8];
#pragma unroll
    for (int i = 0; i < 8; i++) Oacc[i] = make_float4(0.f, 0.f, 0.f, 0.f);
    float m0 = -INFINITY, m1 = -INFINITY, l0 = 0.f, l1 = 0.f;

    const int kbase = (lane >> 2) * 36 + (lane & 3);
    const int vbase = (lane >> 2) * 68 + (lane & 3);

    fill(0, 0); CP_COMMIT();

    for (int j = 0; j < NKV; j++) {
        CP_WAIT0();
        __syncthreads();
        if (j + 1 < NKV) fill((j + 1) & 1, j + 1);
        CP_COMMIT();
        const uint32_t* sb = sm + (j & 1) * ABUF;

        // ---- S2 = (log2e*Q) K^T : log2-domain scores ----
        float4 Sacc[16];
#pragma unroll
        for (int nt = 0; nt < 16; nt++) {
            float4 acc = make_float4(0.f, 0.f, 0.f, 0.f);
            int nb = nt * (8 * 36);
#pragma unroll
            for (int ks = 0; ks < 4; ks++) {
                int wA = kbase + nb + ks * 8;
                uint32_t bh0 = sb[KHI_W + wA], bh1 = sb[KHI_W + wA + 4];
                uint32_t bl0 = sb[KLO_W + wA], bl1 = sb[KLO_W + wA + 4];
                int q = ks * 4;
                mma16816(acc, QH[q], QH[q+1], QH[q+2], QH[q+3], bh0, bh1);
                mma16816(acc, QH[q], QH[q+1], QH[q+2], QH[q+3], bl0, bl1);
                mma16816(acc, QL[q], QL[q+1], QL[q+2], QL[q+3], bh0, bh1);
            }
            Sacc[nt] = acc;
        }

        float mx0 = -INFINITY, mx1 = -INFINITY;
#pragma unroll
        for (int nt = 0; nt < 16; nt++) {
            mx0 = fmaxf(mx0, fmaxf(Sacc[nt].x, Sacc[nt].y));
            mx1 = fmaxf(mx1, fmaxf(Sacc[nt].z, Sacc[nt].w));
        }
        mx0 = fmaxf(mx0, __shfl_xor_sync(0xffffffffu, mx0, 1));
        mx0 = fmaxf(mx0, __shfl_xor_sync(0xffffffffu, mx0, 2));
        mx1 = fmaxf(mx1, __shfl_xor_sync(0xffffffffu, mx1, 1));
        mx1 = fmaxf(mx1, __shfl_xor_sync(0xffffffffu, mx1, 2));
        float mn0 = fmaxf(m0, mx0), mn1 = fmaxf(m1, mx1);

        float s0 = 0.f, s1 = 0.f;
#pragma unroll
        for (int s = 0; s < 8; s++) {
            float4 Sa = Sacc[2 * s], Sb = Sacc[2 * s + 1];
            float pa0 = ex2(Sa.x - mn0), pa1 = ex2(Sa.y - mn0);
            float pa2 = ex2(Sa.z - mn1), pa3 = ex2(Sa.w - mn1);
            float pb0 = ex2(Sb.x - mn0), pb1 = ex2(Sb.y - mn0);
            float pb2 = ex2(Sb.z - mn1), pb3 = ex2(Sb.w - mn1);
            s0 += pa0 + pa1 + pb0 + pb1;
            s1 += pa2 + pa3 + pb2 + pb3;
            uint32_t ah0 = pack_hi(pa0, pa1), al0 = pack_lo(pa0, pa1, ah0);
            uint32_t ah1 = pack_hi(pa2, pa3), al1 = pack_lo(pa2, pa3, ah1);
            uint32_t ah2 = pack_hi(pb0, pb1), al2 = pack_lo(pb0, pb1, ah2);
            uint32_t ah3 = pack_hi(pb2, pb3), al3 = pack_lo(pb2, pb3, ah3);
#pragma unroll
            for (int nt = 0; nt < 8; nt++) {
                int wB = vbase + nt * (8 * 68) + s * 8;
                uint32_t vh0 = sb[VHI_W + wB], vh1 = sb[VHI_W + wB + 4];
                uint32_t vl0 = sb[VLO_W + wB], vl1 = sb[VLO_W + wB + 4];
                mma16816(Oacc[nt], ah0, ah1, ah2, ah3, vh0, vh1);
                mma16816(Oacc[nt], al0, al1, al2, al3, vh0, vh1);
                mma16816(Oacc[nt], ah0, ah1, ah2, ah3, vl0, vl1);
            }
        }

        s0 += __shfl_xor_sync(0xffffffffu, s0, 1);
        s0 += __shfl_xor_sync(0xffffffffu, s0, 2);
        s1 += __shfl_xor_sync(0xffffffffu, s1, 1);
        s1 += __shfl_xor_sync(0xffffffffu, s1, 2);
        l0 = ex2(m0 - mn0) * l0 + s0;   m0 = mn0;
        l1 = ex2(m1 - mn1) * l1 + s1;   m1 = mn1;
    }

    const float inv0 = 1.f / l0, inv1 = 1.f / l1;
    const int rowg = q0 + wid * 16 + r0;
    uint32_t* oh = Oh + ((size_t)b * 4096 + rowg) * 512 + h * 32 + (lane & 3);
    uint32_t* ol = Ol + ((size_t)b * 4096 + rowg) * 512 + h * 32 + (lane & 3);
#pragma unroll
    for (int nt = 0; nt < 8; nt++) {
        float ax = Oacc[nt].x * inv0, ay = Oacc[nt].y * inv0;
        uint32_t hw = pack_hi(ax, ay);
        oh[nt * 4] = hw;  ol[nt * 4] = pack_lo(ax, ay, hw);
        float az = Oacc[nt].z * inv1, aw = Oacc[nt].w * inv1;
        hw = pack_hi(az, aw);
        oh[nt * 4 + 8 * 512] = hw;  ol[nt * 4 + 8 * 512] = pack_lo(az, aw, hw);
    }
}

// ===========================================================================
extern "C" void kernel_launch(void* const* d_in, const int* in_sizes, int n_in,
                              void* d_out, int out_size)
{
    const float* x  = (const float*)d_in[0];
    const float* wq = (const float*)d_in[1];
    const float* bq = (const float*)d_in[2];
    const float* wk = (const float*)d_in[3];
    const float* bk = (const float*)d_in[4];
    const float* wv = (const float*)d_in[5];
    const float* bv = (const float*)d_in[6];
    const float* wo = (const float*)d_in[7];
    const float* bo = (const float*)d_in[8];
    float* out = (float*)d_out;

    uint32_t *xh, *xl, *wh, *wl, *Qh, *Ql, *Kh, *Kl, *Vh, *Vl, *Ohp, *Olp;
    cudaGetSymbolAddress((void**)&xh, g_xh);
    cudaGetSymbolAddress((void**)&xl, g_xl);
    cudaGetSymbolAddress((void**)&wh, g_wh);
    cudaGetSymbolAddress((void**)&wl, g_wl);
    cudaGetSymbolAddress((void**)&Qh, g_Qh);
    cudaGetSymbolAddress((void**)&Ql, g_Ql);
    cudaGetSymbolAddress((void**)&Kh, g_Kh);
    cudaGetSymbolAddress((void**)&Kl, g_Kl);
    cudaGetSymbolAddress((void**)&Vh, g_Vh);
    cudaGetSymbolAddress((void**)&Vl, g_Vl);
    cudaGetSymbolAddress((void**)&Ohp, g_Oh);
    cudaGetSymbolAddress((void**)&Olp, g_Ol);

    cudaFuncSetAttribute(attn_mma,
                         cudaFuncAttributeMaxDynamicSharedMemorySize, SMEM_ATTN_B);
    cudaFuncSetAttribute(gemm_bf16,
                         cudaFuncAttributeMaxDynamicSharedMemorySize, GEMM_SMEM_B);

    const int WW = 1024 * 512;

    cvt_hl<<<16384, 256>>>((const float4*)x, (uint2*)xh, (uint2*)xl, 4194304);
    cvt_w4<<<4096, 256>>>((const float4*)wq, (const float4*)wk,
                          (const float4*)wv, (const float4*)wo,
                          (uint2*)wh, (uint2*)wl);

    dim3 gg(8, 128);
    gemm_bf16<<<gg, 256, GEMM_SMEM_B>>>(xh, xl, wh + 0*WW, wl + 0*WW, bq,
                                        nullptr, Qh, Ql, 1, LOG2E);  // Q pre-scaled
    gemm_bf16<<<gg, 256, GEMM_SMEM_B>>>(xh, xl, wh + 1*WW, wl + 1*WW, bk,
                                        nullptr, Kh, Kl, 1, 1.0f);
    gemm_bf16<<<gg, 256, GEMM_SMEM_B>>>(xh, xl, wh + 2*WW, wl + 2*WW, bv,
                                        nullptr, Vh, Vl, 2, 1.0f);

    attn_mma<<<dim3(32, 64), 256, SMEM_ATTN_B>>>(Qh, Ql, Kh, Kl, Vh, Vl, Ohp, Olp);

    gemm_bf16<<<gg, 256, GEMM_SMEM_B>>>(Ohp, Olp, wh + 3*WW, wl + 3*WW, bo,
                                        out, nullptr, nullptr, 0, 1.0f);
}

// round 15
// speedup vs baseline: 1.0770x; 1.0006x over previous
#include <cuda_runtime.h>
#include <cuda_bf16.h>
#include <math.h>
#include <cstdint>

#define BB   4
#define TT   4096
#define DD   1024
#define HH   16
#define NKV  32
#define LOG2E 1.4426950408889634f

// ---- device scratch (uint32 = bf16x2 words) ----
__device__ uint32_t g_xh [16384 * 512];
__device__ uint32_t g_xl [16384 * 512];
__device__ uint32_t g_wh [4][1024 * 512];
__device__ uint32_t g_wl [4][1024 * 512];
__device__ uint32_t g_Qh [64 * 4096 * 32];  // (b,h,t,d/2) bf16 hi (pre-scaled by log2e)
__device__ uint32_t g_Ql [64 * 4096 * 32];
__device__ uint32_t g_Kh [64 * 4096 * 32];
__device__ uint32_t g_Kl [64 * 4096 * 32];
__device__ uint32_t g_Vh [64 * 64 * 2048];  // (b,h,d,t/2) bf16 hi
__device__ uint32_t g_Vl [64 * 64 * 2048];  // (b,h,d,t/2) bf16 lo
__device__ uint32_t g_Oh [4 * 4096 * 512];  // (b,t,D/2) bf16 hi
__device__ uint32_t g_Ol [4 * 4096 * 512];

// ===========================================================================
// helpers
// ===========================================================================
__device__ __forceinline__ uint32_t smem_u32(const void* p) {
    uint32_t a;
    asm("{ .reg .u64 t; cvta.to.shared.u64 t, %1; cvt.u32.u64 %0, t; }"
        : "=r"(a) : "l"(p));
    return a;
}
__device__ __forceinline__ void cp16(uint32_t dst, const void* src) {
    asm volatile("cp.async.cg.shared.global [%0], [%1], 16;" :: "r"(dst), "l"(src));
}
#define CP_COMMIT() asm volatile("cp.async.commit_group;" ::: "memory")
#define CP_WAIT0()  asm volatile("cp.async.wait_group 0;" ::: "memory")

__device__ __forceinline__ void mma16816(float4& d,
    uint32_t a0, uint32_t a1, uint32_t a2, uint32_t a3,
    uint32_t b0, uint32_t b1)
{
    asm volatile(
        "mma.sync.aligned.m16n8k16.row.col.f32.bf16.bf16.f32 "
        "{%0,%1,%2,%3}, {%4,%5,%6,%7}, {%8,%9}, {%0,%1,%2,%3};"
        : "+f"(d.x), "+f"(d.y), "+f"(d.z), "+f"(d.w)
        : "r"(a0), "r"(a1), "r"(a2), "r"(a3), "r"(b0), "r"(b1));
}
__device__ __forceinline__ uint32_t pack_hi(float a, float b) {
    __nv_bfloat162 t = __floats2bfloat162_rn(a, b);
    return *(uint32_t*)&t;
}
__device__ __forceinline__ uint32_t pack_lo(float a, float b, uint32_t hi) {
    __nv_bfloat162 h = *(__nv_bfloat162*)&hi;
    __nv_bfloat162 t = __floats2bfloat162_rn(a - __bfloat162float(h.x),
                                             b - __bfloat162float(h.y));
    return *(uint32_t*)&t;
}
__device__ __forceinline__ float ex2(float x) {
    float r;
    asm("ex2.approx.f32 %0, %1;" : "=f"(r) : "f"(x));
    return r;
}

// ===========================================================================
// fp32 -> bf16 hi/lo split: x (single) and all-4-weights (merged) variants
// ===========================================================================
__global__ void cvt_hl(const float4* __restrict__ src, uint2* __restrict__ h,
                       uint2* __restrict__ l, int n4)
{
    int i = blockIdx.x * 256 + threadIdx.x;
    if (i >= n4) return;
    float4 v = src[i];
    uint32_t h0 = pack_hi(v.x, v.y), h1 = pack_hi(v.z, v.w);
    h[i] = make_uint2(h0, h1);
    l[i] = make_uint2(pack_lo(v.x, v.y, h0), pack_lo(v.z, v.w, h1));
}
__global__ void cvt_w4(const float4* __restrict__ w0, const float4* __restrict__ w1,
                       const float4* __restrict__ w2, const float4* __restrict__ w3,
                       uint2* __restrict__ h, uint2* __restrict__ l)
{
    int i = blockIdx.x * 256 + threadIdx.x;       // 0 .. 4*262144-1
    int m = i >> 18, o = i & 262143;
    const float4* s = (m == 0) ? w0 : (m == 1) ? w1 : (m == 2) ? w2 : w3;
    float4 v = s[o];
    uint32_t h0 = pack_hi(v.x, v.y), h1 = pack_hi(v.z, v.w);
    h[i] = make_uint2(h0, h1);
    l[i] = make_uint2(pack_lo(v.x, v.y, h0), pack_lo(v.z, v.w, h1));
}

// ===========================================================================
// bf16 hi/lo GEMM, 128x128, 2 CTA/SM, cp.async dbl buffer; ONE barrier per
// K-chunk (bottom barrier removed — top barrier of iter kc already fences
// readers of the buffer fill(kc+1) overwrites).
// mode 0: f32 (B,T,D)  mode 1: bf16 h/l head-split (b,h,t,d), scaled by oscale
// mode 2: bf16 h/l head-split transposed (b,h,d,t)
// ===========================================================================
#define GSTR 20
#define GA_H 0
#define GA_L 2560
#define GW_H 5120
#define GW_L 7680
#define GBUF 10240
#define EP_STR 129
#define GEMM_SMEM_B (2 * GBUF * 4)

__global__ __launch_bounds__(256, 2)
void gemm_bf16(const uint32_t* __restrict__ Ah, const uint32_t* __restrict__ Al,
               const uint32_t* __restrict__ Wh, const uint32_t* __restrict__ Wl,
               const float* __restrict__ bias,
               float* __restrict__ C0, uint32_t* __restrict__ Ch,
               uint32_t* __restrict__ Cl, int mode, float oscale)
{
    extern __shared__ uint32_t sw[];
    const uint32_t sbase = smem_u32(sw);
    const int tid = threadIdx.x, lane = tid & 31, wid = tid >> 5;
    const int wm = wid >> 1, wn = wid & 1;
    const int n0 = blockIdx.x * 128, m0 = blockIdx.y * 128;
    const int r0 = lane >> 2, c2l = lane & 3;

    auto fill = [&](int buf, int kt) {
#pragma unroll
        for (int it = 0; it < 8; it++) {
            int e = tid + it * 256;
            int arr = e >> 9;
            int c = e & 511, row = c >> 2, cw = (c & 3) * 4;
            const uint32_t* g = (arr == 0) ? Ah : (arr == 1) ? Al
                              : (arr == 2) ? Wh : Wl;
            int rbase = (arr < 2) ? m0 : n0;
            uint32_t dw = (uint32_t)(buf * GBUF + arr * 2560 + row * GSTR + cw);
            cp16(sbase + dw * 4, g + (size_t)(rbase + row) * 512 + (kt >> 1) + cw);
        }
    };

    float4 acc[2][8];
#pragma unroll
    for (int mt = 0; mt < 2; mt++)
#pragma unroll
        for (int nt = 0; nt < 8; nt++) acc[mt][nt] = make_float4(0.f, 0.f, 0.f, 0.f);

    fill(0, 0); CP_COMMIT();

    for (int kc = 0; kc < 32; kc++) {
        CP_WAIT0();
        __syncthreads();                 // single barrier per iteration
        if (kc + 1 < 32) fill((kc + 1) & 1, (kc + 1) * 32);
        CP_COMMIT();
        const uint32_t* sb = sw + (kc & 1) * GBUF;

#pragma unroll
        for (int ks = 0; ks < 2; ks++) {
            uint32_t AH[2][4], AL[2][4];
#pragma unroll
            for (int mt = 0; mt < 2; mt++) {
                int aw = (wm * 32 + mt * 16 + r0) * GSTR + c2l + ks * 8;
                AH[mt][0] = sb[GA_H + aw];
                AH[mt][1] = sb[GA_H + aw + 8 * GSTR];
                AH[mt][2] = sb[GA_H + aw + 4];
                AH[mt][3] = sb[GA_H + aw + 8 * GSTR + 4];
                AL[mt][0] = sb[GA_L + aw];
                AL[mt][1] = sb[GA_L + aw + 8 * GSTR];
                AL[mt][2] = sb[GA_L + aw + 4];
                AL[mt][3] = sb[GA_L + aw + 8 * GSTR + 4];
            }
#pragma unroll
            for (int nt = 0; nt < 8; nt++) {
                int bw = (wn * 64 + nt * 8 + r0) * GSTR + c2l + ks * 8;
                uint32_t bh0 = sb[GW_H + bw], bh1 = sb[GW_H + bw + 4];
                uint32_t bl0 = sb[GW_L + bw], bl1 = sb[GW_L + bw + 4];
#pragma unroll
                for (int mt = 0; mt < 2; mt++) {
                    mma16816(acc[mt][nt], AH[mt][0], AH[mt][1], AH[mt][2], AH[mt][3], bh0, bh1);
                    mma16816(acc[mt][nt], AL[mt][0], AL[mt][1], AL[mt][2], AL[mt][3], bh0, bh1);
                    mma16816(acc[mt][nt], AH[mt][0], AH[mt][1], AH[mt][2], AH[mt][3], bl0, bl1);
                }
            }
        }
    }

    // ---- epilogues ----
    if (mode == 0) {
#pragma unroll
        for (int mt = 0; mt < 2; mt++) {
            int rowa = wm * 32 + mt * 16 + r0;
#pragma unroll
            for (int nt = 0; nt < 8; nt++) {
                int col = wn * 64 + nt * 8 + c2l * 2;
                float b0 = bias[n0 + col], b1 = bias[n0 + col + 1];
                *(float2*)&C0[(size_t)(m0 + rowa) * 1024 + n0 + col] =
                    make_float2(acc[mt][nt].x + b0, acc[mt][nt].y + b1);
                *(float2*)&C0[(size_t)(m0 + rowa + 8) * 1024 + n0 + col] =
                    make_float2(acc[mt][nt].z + b0, acc[mt][nt].w + b1);
            }
        }
    } else if (mode == 1) {
#pragma unroll
        for (int mt = 0; mt < 2; mt++) {
            int rowa = wm * 32 + mt * 16 + r0;
            int ma = m0 + rowa;
            int ba = ma >> 12, ta = ma & 4095;
#pragma unroll
            for (int nt = 0; nt < 8; nt++) {
                int col = wn * 64 + nt * 8 + c2l * 2;
                int n = n0 + col, hh = n >> 6, dcol = n & 63;
                float b0 = bias[n], b1 = bias[n + 1];
                float v0x = (acc[mt][nt].x + b0) * oscale;
                float v0y = (acc[mt][nt].y + b1) * oscale;
                float v1x = (acc[mt][nt].z + b0) * oscale;
                float v1y = (acc[mt][nt].w + b1) * oscale;
                size_t w0 = ((size_t)(ba * 16 + hh) * 4096 + ta) * 32 + (dcol >> 1);
                uint32_t hw = pack_hi(v0x, v0y);
                Ch[w0] = hw;  Cl[w0] = pack_lo(v0x, v0y, hw);
                hw = pack_hi(v1x, v1y);
                Ch[w0 + 8 * 32] = hw;  Cl[w0 + 8 * 32] = pack_lo(v1x, v1y, hw);
            }
        }
    } else {
        __syncthreads();
        float* sf = (float*)sw;
#pragma unroll
        for (int mt = 0; mt < 2; mt++) {
            int rowa = wm * 32 + mt * 16 + r0;
#pragma unroll
            for (int nt = 0; nt < 8; nt++) {
                int col = wn * 64 + nt * 8 + c2l * 2;
                float b0 = bias[n0 + col], b1 = bias[n0 + col + 1];
                sf[rowa * EP_STR + col]           = acc[mt][nt].x + b0;
                sf[rowa * EP_STR + col + 1]       = acc[mt][nt].y + b1;
                sf[(rowa + 8) * EP_STR + col]     = acc[mt][nt].z + b0;
                sf[(rowa + 8) * EP_STR + col + 1] = acc[mt][nt].w + b1;
            }
        }
        __syncthreads();
        const int ba = m0 >> 12, t0 = m0 & 4095;
#pragma unroll
        for (int it = 0; it < 16; it++) {
            int e = tid + it * 256;
            int col = e >> 5, r4 = e & 31;
            float o0 = sf[(r4 * 4 + 0) * EP_STR + col];
            float o1 = sf[(r4 * 4 + 1) * EP_STR + col];
            float o2 = sf[(r4 * 4 + 2) * EP_STR + col];
            float o3 = sf[(r4 * 4 + 3) * EP_STR + col];
            int n = n0 + col, hh = n >> 6, dcol = n & 63;
            size_t w = ((size_t)((ba * 16 + hh) * 64 + dcol)) * 2048 + (t0 >> 1) + r4 * 2;
            uint32_t h0 = pack_hi(o0, o1), h1 = pack_hi(o2, o3);
            *(uint2*)&Ch[w] = make_uint2(h0, h1);
            *(uint2*)&Cl[w] = make_uint2(pack_lo(o0, o1, h0), pack_lo(o2, o3, h1));
        }
    }
}

// ===========================================================================
// attention: R14 champion (log2-domain softmax, ex2).
// ===========================================================================
#define KHI_W 0
#define KLO_W 4608          // 128*36
#define VHI_W 9216
#define VLO_W 13568         // + 64*68
#define ABUF  17920
#define SMEM_ATTN_B (2 * ABUF * 4)   // 143360

__global__ __launch_bounds__(256, 1)
void attn_mma(const uint32_t* __restrict__ Qh, const uint32_t* __restrict__ Ql,
              const uint32_t* __restrict__ Kh, const uint32_t* __restrict__ Kl,
              const uint32_t* __restrict__ Vh, const uint32_t* __restrict__ Vl,
              uint32_t* __restrict__ Oh, uint32_t* __restrict__ Ol)
{
    extern __shared__ uint32_t sm[];
    const uint32_t sbase = smem_u32(sm);
    const int tid  = threadIdx.x;
    const int lane = tid & 31, wid = tid >> 5;
    const int bh = blockIdx.y, q0 = blockIdx.x * 128;
    const int b = bh >> 4, h = bh & 15;
    const int r0 = lane >> 2;

    auto fill = [&](int buf, int j) {
#pragma unroll
        for (int it = 0; it < 16; it++) {
            int e = tid + it * 256;
            if (it < 8) {
                int arr = e >> 10;
                int c = e & 1023, row = c >> 3, cw = (c & 7) * 4;
                const uint32_t* g = arr ? Kl : Kh;
                uint32_t dw = (uint32_t)(buf * ABUF + arr * 4608 + row * 36 + cw);
                cp16(sbase + dw * 4,
                     g + ((size_t)bh * 4096 + j * 128 + row) * 32 + cw);
            } else {
                int e2 = e - 2048;
                int arr = e2 >> 10;
                int c = e2 & 1023, row = c >> 4, cw = (c & 15) * 4;
                const uint32_t* g = arr ? Vl : Vh;
                uint32_t dw = (uint32_t)(buf * ABUF + VHI_W + arr * 4352 + row * 68 + cw);
                cp16(sbase + dw * 4,
                     g + ((size_t)bh * 64 + row) * 2048 + j * 64 + cw);
            }
        }
    };

    uint32_t QH[16], QL[16];
    {
        const uint32_t* gqh = Qh + ((size_t)bh * 4096 + q0 + wid * 16) * 32;
        const uint32_t* gql = Ql + ((size_t)bh * 4096 + q0 + wid * 16) * 32;
#pragma unroll
        for (int ks = 0; ks < 4; ks++)
#pragma unroll
            for (int ko = 0; ko < 2; ko++)
#pragma unroll
                for (int ro = 0; ro < 2; ro++) {
                    int off = (r0 + 8 * ro) * 32 + ks * 8 + ko * 4 + (lane & 3);
                    int idx = ks * 4 + ko * 2 + ro;
                    QH[idx] = gqh[off];
                    QL[idx] = gql[off];
                }
    }

    float4 Oacc[8];
#pragma unroll
    for (int i = 0; i < 8; i++) Oacc[i] = make_float4(0.f, 0.f, 0.f, 0.f);
    float m0 = -INFINITY, m1 = -INFINITY, l0 = 0.f, l1 = 0.f;

    const int kbase = (lane >> 2) * 36 + (lane & 3);
    const int vbase = (lane >> 2) * 68 + (lane & 3);

    fill(0, 0); CP_COMMIT();

    for (int j = 0; j < NKV; j++) {
        CP_WAIT0();
        __syncthreads();
        if (j + 1 < NKV) fill((j + 1) & 1, j + 1);
        CP_COMMIT();
        const uint32_t* sb = sm + (j & 1) * ABUF;

        float4 Sacc[16];
#pragma unroll
        for (int nt = 0; nt < 16; nt++) {
            float4 acc = make_float4(0.f, 0.f, 0.f, 0.f);
            int nb = nt * (8 * 36);
#pragma unroll
            for (int ks = 0; ks < 4; ks++) {
                int wA = kbase + nb + ks * 8;
                uint32_t bh0 = sb[KHI_W + wA], bh1 = sb[KHI_W + wA + 4];
                uint32_t bl0 = sb[KLO_W + wA], bl1 = sb[KLO_W + wA + 4];
                int q = ks * 4;
                mma16816(acc, QH[q], QH[q+1], QH[q+2], QH[q+3], bh0, bh1);
                mma16816(acc, QH[q], QH[q+1], QH[q+2], QH[q+3], bl0, bl1);
                mma16816(acc, QL[q], QL[q+1], QL[q+2], QL[q+3], bh0, bh1);
            }
            Sacc[nt] = acc;
        }

        float mx0 = -INFINITY, mx1 = -INFINITY;
#pragma unroll
        for (int nt = 0; nt < 16; nt++) {
            mx0 = fmaxf(mx0, fmaxf(Sacc[nt].x, Sacc[nt].y));
            mx1 = fmaxf(mx1, fmaxf(Sacc[nt].z, Sacc[nt].w));
        }
        mx0 = fmaxf(mx0, __shfl_xor_sync(0xffffffffu, mx0, 1));
        mx0 = fmaxf(mx0, __shfl_xor_sync(0xffffffffu, mx0, 2));
        mx1 = fmaxf(mx1, __shfl_xor_sync(0xffffffffu, mx1, 1));
        mx1 = fmaxf(mx1, __shfl_xor_sync(0xffffffffu, mx1, 2));
        float mn0 = fmaxf(m0, mx0), mn1 = fmaxf(m1, mx1);

        float s0 = 0.f, s1 = 0.f;
#pragma unroll
        for (int s = 0; s < 8; s++) {
            float4 Sa = Sacc[2 * s], Sb = Sacc[2 * s + 1];
            float pa0 = ex2(Sa.x - mn0), pa1 = ex2(Sa.y - mn0);
            float pa2 = ex2(Sa.z - mn1), pa3 = ex2(Sa.w - mn1);
            float pb0 = ex2(Sb.x - mn0), pb1 = ex2(Sb.y - mn0);
            float pb2 = ex2(Sb.z - mn1), pb3 = ex2(Sb.w - mn1);
            s0 += pa0 + pa1 + pb0 + pb1;
            s1 += pa2 + pa3 + pb2 + pb3;
            uint32_t ah0 = pack_hi(pa0, pa1), al0 = pack_lo(pa0, pa1, ah0);
            uint32_t ah1 = pack_hi(pa2, pa3), al1 = pack_lo(pa2, pa3, ah1);
            uint32_t ah2 = pack_hi(pb0, pb1), al2 = pack_lo(pb0, pb1, ah2);
            uint32_t ah3 = pack_hi(pb2, pb3), al3 = pack_lo(pb2, pb3, ah3);
#pragma unroll
            for (int nt = 0; nt < 8; nt++) {
                int wB = vbase + nt * (8 * 68) + s * 8;
                uint32_t vh0 = sb[VHI_W + wB], vh1 = sb[VHI_W + wB + 4];
                uint32_t vl0 = sb[VLO_W + wB], vl1 = sb[VLO_W + wB + 4];
                mma16816(Oacc[nt], ah0, ah1, ah2, ah3, vh0, vh1);
                mma16816(Oacc[nt], al0, al1, al2, al3, vh0, vh1);
                mma16816(Oacc[nt], ah0, ah1, ah2, ah3, vl0, vl1);
            }
        }

        s0 += __shfl_xor_sync(0xffffffffu, s0, 1);
        s0 += __shfl_xor_sync(0xffffffffu, s0, 2);
        s1 += __shfl_xor_sync(0xffffffffu, s1, 1);
        s1 += __shfl_xor_sync(0xffffffffu, s1, 2);
        l0 = ex2(m0 - mn0) * l0 + s0;   m0 = mn0;
        l1 = ex2(m1 - mn1) * l1 + s1;   m1 = mn1;
    }

    const float inv0 = 1.f / l0, inv1 = 1.f / l1;
    const int rowg = q0 + wid * 16 + r0;
    uint32_t* oh = Oh + ((size_t)b * 4096 + rowg) * 512 + h * 32 + (lane & 3);
    uint32_t* ol = Ol + ((size_t)b * 4096 + rowg) * 512 + h * 32 + (lane & 3);
#pragma unroll
    for (int nt = 0; nt < 8; nt++) {
        float ax = Oacc[nt].x * inv0, ay = Oacc[nt].y * inv0;
        uint32_t hw = pack_hi(ax, ay);
        oh[nt * 4] = hw;  ol[nt * 4] = pack_lo(ax, ay, hw);
        float az = Oacc[nt].z * inv1, aw = Oacc[nt].w * inv1;
        hw = pack_hi(az, aw);
        oh[nt * 4 + 8 * 512] = hw;  ol[nt * 4 + 8 * 512] = pack_lo(az, aw, hw);
    }
}

// ===========================================================================
extern "C" void kernel_launch(void* const* d_in, const int* in_sizes, int n_in,
                              void* d_out, int out_size)
{
    const float* x  = (const float*)d_in[0];
    const float* wq = (const float*)d_in[1];
    const float* bq = (const float*)d_in[2];
    const float* wk = (const float*)d_in[3];
    const float* bk = (const float*)d_in[4];
    const float* wv = (const float*)d_in[5];
    const float* bv = (const float*)d_in[6];
    const float* wo = (const float*)d_in[7];
    const float* bo = (const float*)d_in[8];
    float* out = (float*)d_out;

    uint32_t *xh, *xl, *wh, *wl, *Qh, *Ql, *Kh, *Kl, *Vh, *Vl, *Ohp, *Olp;
    cudaGetSymbolAddress((void**)&xh, g_xh);
    cudaGetSymbolAddress((void**)&xl, g_xl);
    cudaGetSymbolAddress((void**)&wh, g_wh);
    cudaGetSymbolAddress((void**)&wl, g_wl);
    cudaGetSymbolAddress((void**)&Qh, g_Qh);
    cudaGetSymbolAddress((void**)&Ql, g_Ql);
    cudaGetSymbolAddress((void**)&Kh, g_Kh);
    cudaGetSymbolAddress((void**)&Kl, g_Kl);
    cudaGetSymbolAddress((void**)&Vh, g_Vh);
    cudaGetSymbolAddress((void**)&Vl, g_Vl);
    cudaGetSymbolAddress((void**)&Ohp, g_Oh);
    cudaGetSymbolAddress((void**)&Olp, g_Ol);

    cudaFuncSetAttribute(attn_mma,
                         cudaFuncAttributeMaxDynamicSharedMemorySize, SMEM_ATTN_B);
    cudaFuncSetAttribute(gemm_bf16,
                         cudaFuncAttributeMaxDynamicSharedMemorySize, GEMM_SMEM_B);

    const int WW = 1024 * 512;

    cvt_hl<<<16384, 256>>>((const float4*)x, (uint2*)xh, (uint2*)xl, 4194304);
    cvt_w4<<<4096, 256>>>((const float4*)wq, (const float4*)wk,
                          (const float4*)wv, (const float4*)wo,
                          (uint2*)wh, (uint2*)wl);

    dim3 gg(8, 128);
    gemm_bf16<<<gg, 256, GEMM_SMEM_B>>>(xh, xl, wh + 0*WW, wl + 0*WW, bq,
                                        nullptr, Qh, Ql, 1, LOG2E);  // Q pre-scaled
    gemm_bf16<<<gg, 256, GEMM_SMEM_B>>>(xh, xl, wh + 1*WW, wl + 1*WW, bk,
                                        nullptr, Kh, Kl, 1, 1.0f);
    gemm_bf16<<<gg, 256, GEMM_SMEM_B>>>(xh, xl, wh + 2*WW, wl + 2*WW, bv,
                                        nullptr, Vh, Vl, 2, 1.0f);

    attn_mma<<<dim3(32, 64), 256, SMEM_ATTN_B>>>(Qh, Ql, Kh, Kl, Vh, Vl, Ohp, Olp);

    gemm_bf16<<<gg, 256, GEMM_SMEM_B>>>(Ohp, Olp, wh + 3*WW, wl + 3*WW, bo,
                                        out, nullptr, nullptr, 0, 1.0f);
}